// round 15
// baseline (speedup 1.0000x reference)
#include <cuda_runtime.h>
#include <cuda_bf16.h>
#include <cstdint>

typedef unsigned long long ull;

#define B_ROWS 16384
#define D_DIM  1024
#define NC     65      // 64 labels + "no-label" extra column
#define CP     80      // padded classes
#define NG1    16      // GEMM1 row groups (1024 rows each)
#define EPSV   1e-8f
#define NEGINF __int_as_float(0xff800000)

// warp-level tensor core helpers (base PTX, lowers to HMMA on sm_103)
#define LDSM_X4(r0, r1, r2, r3, a) \
    asm volatile("ldmatrix.sync.aligned.m8n8.x4.shared.b16 {%0,%1,%2,%3}, [%4];" \
        : "=r"(r0), "=r"(r1), "=r"(r2), "=r"(r3) : "r"(a))
#define LDSM_X2(r0, r1, a) \
    asm volatile("ldmatrix.sync.aligned.m8n8.x2.shared.b16 {%0,%1}, [%2];" \
        : "=r"(r0), "=r"(r1) : "r"(a))
#define LDSM_X4_T(r0, r1, r2, r3, a) \
    asm volatile("ldmatrix.sync.aligned.m8n8.x4.trans.shared.b16 {%0,%1,%2,%3}, [%4];" \
        : "=r"(r0), "=r"(r1), "=r"(r2), "=r"(r3) : "r"(a))
#define MMA_BF16(c, a, b0, b1) \
    asm volatile("mma.sync.aligned.m16n8k16.row.col.f32.bf16.bf16.f32 " \
        "{%0,%1,%2,%3}, {%4,%5,%6,%7}, {%8,%9}, {%0,%1,%2,%3};" \
        : "+f"((c)[0]), "+f"((c)[1]), "+f"((c)[2]), "+f"((c)[3]) \
        : "r"((a)[0]), "r"((a)[1]), "r"((a)[2]), "r"((a)[3]), "r"(b0), "r"(b1))

__device__ __forceinline__ uint32_t smem_u32(const void* p) {
    uint32_t a;
    asm("{ .reg .u64 t; cvta.to.shared.u64 t, %1; cvt.u32.u64 %0, t; }" : "=r"(a) : "l"(p));
    return a;
}

// ---------------- static device scratch ----------------
__device__ ull    g_mask[B_ROWS];
__device__ int    g_cntp[64][65];
__device__ float  g_part[NG1][CP][D_DIM];   // GEMM1 partial sums (5.2 MB)
__device__ __nv_bfloat16 g_aHi[CP][D_DIM];
__device__ __nv_bfloat16 g_aLo[CP][D_DIM];
__device__ float  g_actInf[CP];
__device__ double g_lossSum;
__device__ long long g_npairs;
__device__ unsigned g_done;

// ---------------- meta: labels -> masks, per-block class counts, zero accumulators ----------------
__global__ void k_meta(const int* __restrict__ label) {
    __shared__ int s_cnt[65];
    int tid = threadIdx.x, b = blockIdx.x, lane = tid & 31;
    int row = b * 256 + tid;

    const uint4* lr = (const uint4*)(label + (size_t)row * 64);
    ull m = 0ull;
#pragma unroll
    for (int i = 0; i < 16; i++) {
        uint4 v = lr[i];
        m |= ((ull)(v.x != 0) << (4 * i))     | ((ull)(v.y != 0) << (4 * i + 1))
           | ((ull)(v.z != 0) << (4 * i + 2)) | ((ull)(v.w != 0) << (4 * i + 3));
    }
    g_mask[row] = m;

    if (tid < 65) s_cnt[tid] = 0;
    __syncthreads();

    int ca = 0, cb = 0, cz = 0;
#pragma unroll
    for (int c = 0; c < 32; c++) {
        unsigned bal = __ballot_sync(~0u, (int)((m >> c) & 1ull));
        if (lane == c) ca = __popc(bal);
    }
#pragma unroll
    for (int c = 32; c < 64; c++) {
        unsigned bal = __ballot_sync(~0u, (int)((m >> c) & 1ull));
        if (lane == c - 32) cb = __popc(bal);
    }
    {
        unsigned bal = __ballot_sync(~0u, m == 0ull);
        if (lane == 0) cz = __popc(bal);
    }
    atomicAdd(&s_cnt[lane], ca);
    atomicAdd(&s_cnt[lane + 32], cb);
    if (lane == 0) atomicAdd(&s_cnt[64], cz);
    __syncthreads();
    if (tid < 65) g_cntp[b][tid] = s_cnt[tid];
    if (b == 0 && tid == 0) { g_lossSum = 0.0; g_done = 0u; }
}

// ---------------- GEMM1 via warp-MMA, 64-d tiles, 2 CTAs/SM (R13 version) ----------------
// grid (16 dtiles, 16 rowgroups) = 256 CTAs, 256 threads = 2 m-groups x 4 n-groups.
#define G1_XH 0        // [64 r][144 B]
#define G1_XL 9216
#define G1_A  18432    // [96 c][128 B] swizzled
#define G1_SZ 30720

__global__ __launch_bounds__(256, 2)
void k_gemm1_mma(const float* __restrict__ x) {
    extern __shared__ __align__(16) char sm[];
    const uint32_t sbase = smem_u32(sm);
    const int tid = threadIdx.x, wid = tid >> 5, lane = tid & 31;
    const int wm = wid & 1, wn = wid >> 1;
    const int d0 = blockIdx.x * 64;
    const int R0 = blockIdx.y * 1024;

    float acc[3][2][4];
#pragma unroll
    for (int i = 0; i < 3; i++)
#pragma unroll
        for (int j = 0; j < 2; j++)
#pragma unroll
            for (int e = 0; e < 4; e++) acc[i][j][e] = 0.f;

    const int lsub = lane >> 3, lrr = lane & 7;
    const int arow = lrr + (lsub & 1) * 8;
    const int kgrp = lsub >> 1;
    const int bk  = (lsub & 1) * 8 + lrr;
    const int bn8 = (lsub >> 1) * 8;
    const int k2 = tid & 31;
    const int t16 = tid & 15, rq = tid >> 4;

    // prefetch chunk 0
    float4 pf[4];
#pragma unroll
    for (int j = 0; j < 4; j++)
        pf[j] = *(const float4*)(x + (size_t)(R0 + rq + 16 * j) * D_DIM + d0 + 4 * t16);

#pragma unroll 1
    for (int ch = 0; ch < 16; ch++) {
        const int R = R0 + ch * 64;
        __syncthreads();
#pragma unroll
        for (int j = 0; j < 4; j++) {
            int r = rq + 16 * j;
            float4 v = pf[j];
            __nv_bfloat16 h0 = __float2bfloat16(v.x), h1 = __float2bfloat16(v.y);
            __nv_bfloat16 h2 = __float2bfloat16(v.z), h3 = __float2bfloat16(v.w);
            uint32_t off = (uint32_t)(r * 144 + t16 * 8);
            __nv_bfloat162 w0; w0.x = h0; w0.y = h1;
            __nv_bfloat162 w1; w1.x = h2; w1.y = h3;
            *(__nv_bfloat162*)(sm + G1_XH + off)     = w0;
            *(__nv_bfloat162*)(sm + G1_XH + off + 4) = w1;
            w0.x = __float2bfloat16(v.x - __bfloat162float(h0));
            w0.y = __float2bfloat16(v.y - __bfloat162float(h1));
            w1.x = __float2bfloat16(v.z - __bfloat162float(h2));
            w1.y = __float2bfloat16(v.w - __bfloat162float(h3));
            *(__nv_bfloat162*)(sm + G1_XL + off)     = w0;
            *(__nv_bfloat162*)(sm + G1_XL + off + 4) = w1;
        }
        {
            ull m0 = g_mask[R + 2 * k2], m1 = g_mask[R + 2 * k2 + 1];
#pragma unroll
            for (int j = 0; j < 12; j++) {
                int c = (tid >> 5) + 8 * j;
                uint32_t w = 0;
                if (c < 64)
                    w = (((m0 >> c) & 1ull) ? 0x3F80u : 0u) | (((m1 >> c) & 1ull) ? 0x3F800000u : 0u);
                else if (c == 64)
                    w = ((m0 == 0ull) ? 0x3F80u : 0u) | ((m1 == 0ull) ? 0x3F800000u : 0u);
                uint32_t off = (uint32_t)(c * 128 + (((k2 >> 2) ^ (c & 7)) << 4) + ((k2 & 3) << 2));
                *(uint32_t*)(sm + G1_A + off) = w;
            }
        }
        __syncthreads();

        if (ch < 15) {
            const float* xp = x + (size_t)(R + 64 + rq) * D_DIM + d0 + 4 * t16;
#pragma unroll
            for (int j = 0; j < 4; j++)
                pf[j] = *(const float4*)(xp + (size_t)(16 * j) * D_DIM);
        }

#pragma unroll
        for (int ks = 0; ks < 4; ks++) {
            const int kc8 = 2 * ks + kgrp;
            uint32_t af[3][4];
#pragma unroll
            for (int mt = 0; mt < 3; mt++) {
                int row = wm * 48 + mt * 16 + arow;
                uint32_t ab = (uint32_t)(row * 128 + ((kc8 ^ (row & 7)) << 4));
                LDSM_X4(af[mt][0], af[mt][1], af[mt][2], af[mt][3], sbase + G1_A + ab);
            }
            uint32_t bh[4], bl[4];
            {
                uint32_t ab = (uint32_t)((ks * 16 + bk) * 144 + (wn * 16 + bn8) * 2);
                LDSM_X4_T(bh[0], bh[1], bh[2], bh[3], sbase + G1_XH + ab);
                LDSM_X4_T(bl[0], bl[1], bl[2], bl[3], sbase + G1_XL + ab);
            }
#pragma unroll
            for (int mt = 0; mt < 3; mt++)
#pragma unroll
                for (int nt = 0; nt < 2; nt++) {
                    MMA_BF16(acc[mt][nt], af[mt], bh[2 * nt], bh[2 * nt + 1]);
                    MMA_BF16(acc[mt][nt], af[mt], bl[2 * nt], bl[2 * nt + 1]);
                }
        }
    }

    const int g = blockIdx.y;
    int crow = wm * 48 + (lane >> 2);
    int ccol = (lane & 3) * 2;
#pragma unroll
    for (int mt = 0; mt < 3; mt++) {
        int c0 = crow + mt * 16;
#pragma unroll
        for (int nt = 0; nt < 2; nt++) {
            int d = d0 + wn * 16 + nt * 8 + ccol;
            if (c0 < NC) {
                g_part[g][c0][d]     = acc[mt][nt][0];
                g_part[g][c0][d + 1] = acc[mt][nt][1];
            }
            if (c0 + 8 < NC) {
                g_part[g][c0 + 8][d]     = acc[mt][nt][2];
                g_part[g][c0 + 8][d + 1] = acc[mt][nt][3];
            }
        }
    }
}

// ---------------- reduce partials -> normalized bf16 hi/lo anchors (+ npairs) ----------------
__global__ void k_anchor() {
    int c = blockIdx.x;
    int tid = threadIdx.x;
    __shared__ float sred[32];
    __shared__ float s_scale;
    __shared__ int s_count;

    if (c >= NC) {
        if (tid < D_DIM) {
            g_aHi[c][tid] = __float2bfloat16(0.f);
            g_aLo[c][tid] = __float2bfloat16(0.f);
        }
        if (tid == 0) {
            g_actInf[c] = NEGINF;
            if (c == CP - 1) {
                long long np = 0;
                for (int b = 0; b < 64; b++)
                    for (int cc = 0; cc < 65; cc++) np += g_cntp[b][cc];
                g_npairs = np;
            }
        }
        return;
    }
    if (tid == 0) {
        int t = 0;
#pragma unroll
        for (int b = 0; b < 64; b++) t += g_cntp[b][c];
        s_count = t;
    }
    __syncthreads();
    int cnt = s_count;
    float inv = 1.0f / (float)max(cnt, 1);

    float s = 0.f;
#pragma unroll
    for (int g = 0; g < NG1; g++) s += g_part[g][c][tid];
    float a = s * inv;
    float ss = a * a;
#pragma unroll
    for (int o = 16; o; o >>= 1) ss += __shfl_xor_sync(~0u, ss, o);
    if ((tid & 31) == 0) sred[tid >> 5] = ss;
    __syncthreads();
    if (tid == 0) {
        float t = 0.f;
        for (int i = 0; i < 32; i++) t += sred[i];
        s_scale = 1.0f / fmaxf(sqrtf(t), EPSV);
        g_actInf[c] = (cnt > 0) ? 0.f : NEGINF;
    }
    __syncthreads();
    float av = a * s_scale;
    __nv_bfloat16 h = __float2bfloat16(av);
    g_aHi[c][tid] = h;
    g_aLo[c][tid] = __float2bfloat16(av - __bfloat162float(h));
}

// ---------------- GEMM2: double-buffered warp-MMA + fused epilogue + last-CTA finalize ----------------
#define S2_XH0 0
#define S2_XL0 8192
#define S2_XH1 16384
#define S2_XL1 24576
#define S2_B0  32768    // BH0; BL0 at +12288
#define S2_B1  57344    // BH1; BL1 at +12288
#define S2_LS  81920
#define S2_NRM 81984
#define S2_SZ  82240

__global__ __launch_bounds__(256, 2)
void k_gemm2_mma(const float* __restrict__ x,
                 const float* __restrict__ wp, const float* __restrict__ bp,
                 float* __restrict__ out) {
    extern __shared__ __align__(16) char sm[];
    const uint32_t sbase = smem_u32(sm);
    const int tid = threadIdx.x, wid = tid >> 5, lane = tid & 31;
    const int wr = wid & 3, wc = wid >> 2;
    const int rbase = blockIdx.x * 64;

    float acc[5][4];
#pragma unroll
    for (int j = 0; j < 5; j++)
#pragma unroll
        for (int e = 0; e < 4; e++) acc[j][e] = 0.f;

    float fsq[4];
#pragma unroll
    for (int j = 0; j < 4; j++) fsq[j] = 0.f;

    const int lsub = lane >> 3, lrr = lane & 7;
    const int arow_off = lrr + (lsub & 1) * 8;
    const int kgrp_sel = lsub >> 1;
    const int t16 = tid & 15, rq = tid >> 4;
    const int ki = 2 * t16;
    const int l16 = lane & 15;
    const int n2row = wc * 40 + 32 + (l16 & 7);
    const int kh2 = l16 >> 3;

    float4 pfx[4];
    uint2 pbh[5], pbl[5];

    // ---- prologue: load + store chunk 0 into buffer 0 ----
#pragma unroll
    for (int j = 0; j < 4; j++)
        pfx[j] = *(const float4*)(x + (size_t)(rbase + rq + 16 * j) * D_DIM + 4 * t16);
#pragma unroll
    for (int j = 0; j < 5; j++) {
        int c = (tid >> 4) + 16 * j;
        pbh[j] = *(const uint2*)&g_aHi[c][2 * ki];
        pbl[j] = *(const uint2*)&g_aLo[c][2 * ki];
    }
#pragma unroll
    for (int j = 0; j < 4; j++) {
        int r = rq + 16 * j;
        float4 v = pfx[j];
        fsq[j] += v.x * v.x + v.y * v.y + v.z * v.z + v.w * v.w;
        uint32_t off = (uint32_t)(r * 128 + (((ki >> 2) ^ (r & 7)) << 4) + ((ki & 3) << 2));
        __nv_bfloat16 h0 = __float2bfloat16(v.x), h1 = __float2bfloat16(v.y);
        __nv_bfloat16 h2 = __float2bfloat16(v.z), h3 = __float2bfloat16(v.w);
        __nv_bfloat162 w0; w0.x = h0; w0.y = h1;
        __nv_bfloat162 w1; w1.x = h2; w1.y = h3;
        *(__nv_bfloat162*)(sm + S2_XH0 + off)     = w0;
        *(__nv_bfloat162*)(sm + S2_XH0 + off + 4) = w1;
        w0.x = __float2bfloat16(v.x - __bfloat162float(h0));
        w0.y = __float2bfloat16(v.y - __bfloat162float(h1));
        w1.x = __float2bfloat16(v.z - __bfloat162float(h2));
        w1.y = __float2bfloat16(v.w - __bfloat162float(h3));
        *(__nv_bfloat162*)(sm + S2_XL0 + off)     = w0;
        *(__nv_bfloat162*)(sm + S2_XL0 + off + 4) = w1;
    }
#pragma unroll
    for (int j = 0; j < 5; j++) {
        int c = (tid >> 4) + 16 * j;
        uint32_t off = (uint32_t)(c * 128 + (((ki >> 2) ^ (c & 7)) << 4) + ((ki & 3) << 2));
        *(uint2*)(sm + S2_B0 + off) = pbh[j];
        *(uint2*)(sm + S2_B0 + 12288 + off) = pbl[j];
    }
    __syncthreads();

#pragma unroll 1
    for (int ch = 0; ch < 16; ch++) {
        const uint32_t bx = (ch & 1) ? 16384u : 0u;           // XH base; XL = +8192
        const uint32_t bb = (ch & 1) ? (uint32_t)S2_B1 : (uint32_t)S2_B0;

        if (ch < 15) {
            const int dn = (ch + 1) * 64;
            const float* xp = x + (size_t)(rbase + rq) * D_DIM + dn + 4 * t16;
#pragma unroll
            for (int j = 0; j < 4; j++)
                pfx[j] = *(const float4*)(xp + (size_t)(16 * j) * D_DIM);
#pragma unroll
            for (int j = 0; j < 5; j++) {
                int c = (tid >> 4) + 16 * j;
                pbh[j] = *(const uint2*)&g_aHi[c][dn + 2 * ki];
                pbl[j] = *(const uint2*)&g_aLo[c][dn + 2 * ki];
            }
        }

#pragma unroll
        for (int ks = 0; ks < 4; ks++) {
            const int kc8 = 2 * ks + kgrp_sel;
            uint32_t fh[4], fl[4];
            {
                int row = wr * 16 + arow_off;
                uint32_t ab = (uint32_t)(row * 128 + ((kc8 ^ (row & 7)) << 4));
                LDSM_X4(fh[0], fh[1], fh[2], fh[3], sbase + bx + ab);
                LDSM_X4(fl[0], fl[1], fl[2], fl[3], sbase + bx + 8192 + ab);
            }
            uint32_t bhf[2][4], blf[2][4];
#pragma unroll
            for (int p = 0; p < 2; p++) {
                int n = wc * 40 + p * 16 + arow_off;
                uint32_t ab = (uint32_t)(n * 128 + ((kc8 ^ (n & 7)) << 4));
                LDSM_X4(bhf[p][0], bhf[p][1], bhf[p][2], bhf[p][3], sbase + bb + ab);
                LDSM_X4(blf[p][0], blf[p][1], blf[p][2], blf[p][3], sbase + bb + 12288 + ab);
            }
            uint32_t bh2[2], bl2[2];
            {
                const int kc8b = 2 * ks + kh2;
                uint32_t ab2 = (uint32_t)(n2row * 128 + ((kc8b ^ (n2row & 7)) << 4));
                LDSM_X2(bh2[0], bh2[1], sbase + bb + ab2);
                LDSM_X2(bl2[0], bl2[1], sbase + bb + 12288 + ab2);
            }
#pragma unroll
            for (int nt = 0; nt < 4; nt++) {
                int p = nt >> 1, w2 = nt & 1;
                MMA_BF16(acc[nt], fh, bhf[p][w2], bhf[p][2 + w2]);
                MMA_BF16(acc[nt], fh, blf[p][w2], blf[p][2 + w2]);
                MMA_BF16(acc[nt], fl, bhf[p][w2], bhf[p][2 + w2]);
            }
            MMA_BF16(acc[4], fh, bh2[0], bh2[1]);
            MMA_BF16(acc[4], fh, bl2[0], bl2[1]);
            MMA_BF16(acc[4], fl, bh2[0], bh2[1]);
        }

        if (ch < 15) {
            const uint32_t nx = (ch & 1) ? 0u : 16384u;
            const uint32_t nb = (ch & 1) ? (uint32_t)S2_B0 : (uint32_t)S2_B1;
#pragma unroll
            for (int j = 0; j < 4; j++) {
                int r = rq + 16 * j;
                float4 v = pfx[j];
                fsq[j] += v.x * v.x + v.y * v.y + v.z * v.z + v.w * v.w;
                uint32_t off = (uint32_t)(r * 128 + (((ki >> 2) ^ (r & 7)) << 4) + ((ki & 3) << 2));
                __nv_bfloat16 h0 = __float2bfloat16(v.x), h1 = __float2bfloat16(v.y);
                __nv_bfloat16 h2 = __float2bfloat16(v.z), h3 = __float2bfloat16(v.w);
                __nv_bfloat162 w0; w0.x = h0; w0.y = h1;
                __nv_bfloat162 w1; w1.x = h2; w1.y = h3;
                *(__nv_bfloat162*)(sm + nx + off)            = w0;
                *(__nv_bfloat162*)(sm + nx + off + 4)        = w1;
                w0.x = __float2bfloat16(v.x - __bfloat162float(h0));
                w0.y = __float2bfloat16(v.y - __bfloat162float(h1));
                w1.x = __float2bfloat16(v.z - __bfloat162float(h2));
                w1.y = __float2bfloat16(v.w - __bfloat162float(h3));
                *(__nv_bfloat162*)(sm + nx + 8192 + off)     = w0;
                *(__nv_bfloat162*)(sm + nx + 8192 + off + 4) = w1;
            }
#pragma unroll
            for (int j = 0; j < 5; j++) {
                int c = (tid >> 4) + 16 * j;
                uint32_t off = (uint32_t)(c * 128 + (((ki >> 2) ^ (c & 7)) << 4) + ((ki & 3) << 2));
                *(uint2*)(sm + nb + off) = pbh[j];
                *(uint2*)(sm + nb + 12288 + off) = pbl[j];
            }
        }
        __syncthreads();
    }

    // row norms
#pragma unroll
    for (int j = 0; j < 4; j++) {
        float s = fsq[j];
        s += __shfl_xor_sync(~0u, s, 8);
        s += __shfl_xor_sync(~0u, s, 4);
        s += __shfl_xor_sync(~0u, s, 2);
        s += __shfl_xor_sync(~0u, s, 1);
        if (t16 == 0)
            *(float*)(sm + S2_NRM + (rq + 16 * j) * 4) = 1.0f / fmaxf(sqrtf(s), EPSV);
    }

    __syncthreads();
    float* sd = (float*)sm;      // [64][81] = 20736 B, overlays X buffers
    {
        int g = lane >> 2, t = lane & 3;
#pragma unroll
        for (int nt = 0; nt < 5; nt++) {
            int r0 = wr * 16 + g;
            int col = wc * 40 + nt * 8 + 2 * t;
            sd[r0 * 81 + col]           = acc[nt][0];
            sd[r0 * 81 + col + 1]       = acc[nt][1];
            sd[(r0 + 8) * 81 + col]     = acc[nt][2];
            sd[(r0 + 8) * 81 + col + 1] = acc[nt][3];
        }
    }
    __syncthreads();

    float wv = *wp, bv = *bp;
    double wl = 0.0;
    float aI0 = g_actInf[lane];
    float aI1 = g_actInf[lane + 32];
    float aI2 = (lane < 16) ? g_actInf[lane + 64] : NEGINF;

    for (int i = 0; i < 8; i++) {
        int rl = wid * 8 + i;
        int rg = rbase + rl;
        float xni = *(const float*)(sm + S2_NRM + rl * 4);
        ull m = g_mask[rg];
        float sw = xni * wv;

        float v0 = sd[rl * 81 + lane] * sw + bv + aI0;
        float v1 = sd[rl * 81 + lane + 32] * sw + bv + aI1;
        float v2 = (lane < 16) ? (sd[rl * 81 + lane + 64] * sw + bv + aI2) : NEGINF;

        float mx = fmaxf(v0, fmaxf(v1, v2));
#pragma unroll
        for (int o = 16; o; o >>= 1) mx = fmaxf(mx, __shfl_xor_sync(~0u, mx, o));

        float se = expf(v0 - mx) + expf(v1 - mx) + ((lane < 16) ? expf(v2 - mx) : 0.f);
#pragma unroll
        for (int o = 16; o; o >>= 1) se += __shfl_xor_sync(~0u, se, o);
        float lse = mx + logf(se);

        int b0 = (int)((m >> lane) & 1ull);
        int b1 = (int)((m >> (lane + 32)) & 1ull);
        int b2 = (lane == 0) ? (int)(m == 0ull) : 0;
        float sv = (b0 ? v0 : 0.f) + (b1 ? v1 : 0.f) + (b2 ? v2 : 0.f);
        int np = b0 + b1 + b2;
#pragma unroll
        for (int o = 16; o; o >>= 1) {
            sv += __shfl_xor_sync(~0u, sv, o);
            np += __shfl_xor_sync(~0u, np, o);
        }
        if (lane == 0) wl += (double)((float)np * lse - sv);
    }
    if (lane == 0) *(double*)(sm + S2_LS + wid * 8) = wl;
    __syncthreads();
    if (tid == 0) {
        double t = 0.0;
        for (int i = 0; i < 8; i++) t += *(double*)(sm + S2_LS + i * 8);
        atomicAdd(&g_lossSum, t);
        __threadfence();
        unsigned prev = atomicAdd(&g_done, 1u);
        if (prev == gridDim.x - 1) {
            double ls = atomicAdd(&g_lossSum, 0.0);   // coherent read
            out[0] = (float)(ls / (double)g_npairs);
        }
    }
}

// ---------------- launcher ----------------
extern "C" void kernel_launch(void* const* d_in, const int* in_sizes, int n_in,
                              void* d_out, int out_size) {
    const float* x = nullptr;
    const int* label = nullptr;
    const float* wp = nullptr;
    const float* bp = nullptr;
    for (int i = 0; i < n_in; i++) {
        if (in_sizes[i] == B_ROWS * D_DIM) x = (const float*)d_in[i];
        else if (in_sizes[i] == B_ROWS * 64) label = (const int*)d_in[i];
        else if (in_sizes[i] == 1) {
            if (!wp) wp = (const float*)d_in[i];
            else bp = (const float*)d_in[i];
        }
    }
    static int smem_set = 0;
    if (!smem_set) {
        cudaFuncSetAttribute(k_gemm2_mma, cudaFuncAttributeMaxDynamicSharedMemorySize, S2_SZ);
        cudaFuncSetAttribute(k_gemm1_mma, cudaFuncAttributeMaxDynamicSharedMemorySize, G1_SZ);
        smem_set = 1;
    }

    k_meta<<<64, 256>>>(label);
    k_gemm1_mma<<<dim3(16, NG1), 256, G1_SZ>>>(x);
    k_anchor<<<CP, 1024>>>();
    k_gemm2_mma<<<B_ROWS / 64, 256, S2_SZ>>>(x, wp, bp, (float*)d_out);
}

// round 16
// speedup vs baseline: 1.5131x; 1.5131x over previous
#include <cuda_runtime.h>
#include <cuda_bf16.h>
#include <cstdint>

typedef unsigned long long ull;

#define B_ROWS 16384
#define D_DIM  1024
#define NC     65      // 64 labels + "no-label" extra column
#define CP     80      // padded classes
#define NG1    16      // GEMM1 row groups (1024 rows each)
#define EPSV   1e-8f
#define NEGINF __int_as_float(0xff800000)

// warp-level tensor core helpers (base PTX, lowers to HMMA on sm_103)
#define LDSM_X4(r0, r1, r2, r3, a) \
    asm volatile("ldmatrix.sync.aligned.m8n8.x4.shared.b16 {%0,%1,%2,%3}, [%4];" \
        : "=r"(r0), "=r"(r1), "=r"(r2), "=r"(r3) : "r"(a))
#define LDSM_X2(r0, r1, a) \
    asm volatile("ldmatrix.sync.aligned.m8n8.x2.shared.b16 {%0,%1}, [%2];" \
        : "=r"(r0), "=r"(r1) : "r"(a))
#define LDSM_X4_T(r0, r1, r2, r3, a) \
    asm volatile("ldmatrix.sync.aligned.m8n8.x4.trans.shared.b16 {%0,%1,%2,%3}, [%4];" \
        : "=r"(r0), "=r"(r1), "=r"(r2), "=r"(r3) : "r"(a))
#define MMA_BF16(c, a, b0, b1) \
    asm volatile("mma.sync.aligned.m16n8k16.row.col.f32.bf16.bf16.f32 " \
        "{%0,%1,%2,%3}, {%4,%5,%6,%7}, {%8,%9}, {%0,%1,%2,%3};" \
        : "+f"((c)[0]), "+f"((c)[1]), "+f"((c)[2]), "+f"((c)[3]) \
        : "r"((a)[0]), "r"((a)[1]), "r"((a)[2]), "r"((a)[3]), "r"(b0), "r"(b1))

__device__ __forceinline__ uint32_t smem_u32(const void* p) {
    uint32_t a;
    asm("{ .reg .u64 t; cvta.to.shared.u64 t, %1; cvt.u32.u64 %0, t; }" : "=r"(a) : "l"(p));
    return a;
}

// ---------------- static device scratch ----------------
__device__ ull    g_mask[B_ROWS];
__device__ int    g_cntp[64][65];
__device__ float  g_part[NG1][CP][D_DIM];   // GEMM1 partial sums (5.2 MB)
__device__ __nv_bfloat16 g_aHi[CP][D_DIM];
__device__ __nv_bfloat16 g_aLo[CP][D_DIM];
__device__ float  g_actInf[CP];
__device__ double g_lossSum;
__device__ long long g_npairs;
__device__ unsigned g_done;

// ---------------- meta: labels -> masks, per-block class counts, zero accumulators ----------------
__global__ void k_meta(const int* __restrict__ label) {
    __shared__ int s_cnt[65];
    int tid = threadIdx.x, b = blockIdx.x, lane = tid & 31;
    int row = b * 256 + tid;

    const uint4* lr = (const uint4*)(label + (size_t)row * 64);
    ull m = 0ull;
#pragma unroll
    for (int i = 0; i < 16; i++) {
        uint4 v = lr[i];
        m |= ((ull)(v.x != 0) << (4 * i))     | ((ull)(v.y != 0) << (4 * i + 1))
           | ((ull)(v.z != 0) << (4 * i + 2)) | ((ull)(v.w != 0) << (4 * i + 3));
    }
    g_mask[row] = m;

    if (tid < 65) s_cnt[tid] = 0;
    __syncthreads();

    int ca = 0, cb = 0, cz = 0;
#pragma unroll
    for (int c = 0; c < 32; c++) {
        unsigned bal = __ballot_sync(~0u, (int)((m >> c) & 1ull));
        if (lane == c) ca = __popc(bal);
    }
#pragma unroll
    for (int c = 32; c < 64; c++) {
        unsigned bal = __ballot_sync(~0u, (int)((m >> c) & 1ull));
        if (lane == c - 32) cb = __popc(bal);
    }
    {
        unsigned bal = __ballot_sync(~0u, m == 0ull);
        if (lane == 0) cz = __popc(bal);
    }
    atomicAdd(&s_cnt[lane], ca);
    atomicAdd(&s_cnt[lane + 32], cb);
    if (lane == 0) atomicAdd(&s_cnt[64], cz);
    __syncthreads();
    if (tid < 65) g_cntp[b][tid] = s_cnt[tid];
    if (b == 0 && tid == 0) { g_lossSum = 0.0; g_done = 0u; }
}

// ---------------- GEMM1 via warp-MMA, 64-d tiles, 2 CTAs/SM (R13 version) ----------------
// grid (16 dtiles, 16 rowgroups) = 256 CTAs, 256 threads = 2 m-groups x 4 n-groups.
#define G1_XH 0        // [64 r][144 B]
#define G1_XL 9216
#define G1_A  18432    // [96 c][128 B] swizzled
#define G1_SZ 30720

__global__ __launch_bounds__(256, 2)
void k_gemm1_mma(const float* __restrict__ x) {
    extern __shared__ __align__(16) char sm[];
    const uint32_t sbase = smem_u32(sm);
    const int tid = threadIdx.x, wid = tid >> 5, lane = tid & 31;
    const int wm = wid & 1, wn = wid >> 1;
    const int d0 = blockIdx.x * 64;
    const int R0 = blockIdx.y * 1024;

    float acc[3][2][4];
#pragma unroll
    for (int i = 0; i < 3; i++)
#pragma unroll
        for (int j = 0; j < 2; j++)
#pragma unroll
            for (int e = 0; e < 4; e++) acc[i][j][e] = 0.f;

    const int lsub = lane >> 3, lrr = lane & 7;
    const int arow = lrr + (lsub & 1) * 8;
    const int kgrp = lsub >> 1;
    const int bk  = (lsub & 1) * 8 + lrr;
    const int bn8 = (lsub >> 1) * 8;
    const int k2 = tid & 31;
    const int t16 = tid & 15, rq = tid >> 4;

    // prefetch chunk 0
    float4 pf[4];
#pragma unroll
    for (int j = 0; j < 4; j++)
        pf[j] = *(const float4*)(x + (size_t)(R0 + rq + 16 * j) * D_DIM + d0 + 4 * t16);

#pragma unroll 1
    for (int ch = 0; ch < 16; ch++) {
        const int R = R0 + ch * 64;
        __syncthreads();
#pragma unroll
        for (int j = 0; j < 4; j++) {
            int r = rq + 16 * j;
            float4 v = pf[j];
            __nv_bfloat16 h0 = __float2bfloat16(v.x), h1 = __float2bfloat16(v.y);
            __nv_bfloat16 h2 = __float2bfloat16(v.z), h3 = __float2bfloat16(v.w);
            uint32_t off = (uint32_t)(r * 144 + t16 * 8);
            __nv_bfloat162 w0; w0.x = h0; w0.y = h1;
            __nv_bfloat162 w1; w1.x = h2; w1.y = h3;
            *(__nv_bfloat162*)(sm + G1_XH + off)     = w0;
            *(__nv_bfloat162*)(sm + G1_XH + off + 4) = w1;
            w0.x = __float2bfloat16(v.x - __bfloat162float(h0));
            w0.y = __float2bfloat16(v.y - __bfloat162float(h1));
            w1.x = __float2bfloat16(v.z - __bfloat162float(h2));
            w1.y = __float2bfloat16(v.w - __bfloat162float(h3));
            *(__nv_bfloat162*)(sm + G1_XL + off)     = w0;
            *(__nv_bfloat162*)(sm + G1_XL + off + 4) = w1;
        }
        {
            ull m0 = g_mask[R + 2 * k2], m1 = g_mask[R + 2 * k2 + 1];
#pragma unroll
            for (int j = 0; j < 12; j++) {
                int c = (tid >> 5) + 8 * j;
                uint32_t w = 0;
                if (c < 64)
                    w = (((m0 >> c) & 1ull) ? 0x3F80u : 0u) | (((m1 >> c) & 1ull) ? 0x3F800000u : 0u);
                else if (c == 64)
                    w = ((m0 == 0ull) ? 0x3F80u : 0u) | ((m1 == 0ull) ? 0x3F800000u : 0u);
                uint32_t off = (uint32_t)(c * 128 + (((k2 >> 2) ^ (c & 7)) << 4) + ((k2 & 3) << 2));
                *(uint32_t*)(sm + G1_A + off) = w;
            }
        }
        __syncthreads();

        if (ch < 15) {
            const float* xp = x + (size_t)(R + 64 + rq) * D_DIM + d0 + 4 * t16;
#pragma unroll
            for (int j = 0; j < 4; j++)
                pf[j] = *(const float4*)(xp + (size_t)(16 * j) * D_DIM);
        }

#pragma unroll
        for (int ks = 0; ks < 4; ks++) {
            const int kc8 = 2 * ks + kgrp;
            uint32_t af[3][4];
#pragma unroll
            for (int mt = 0; mt < 3; mt++) {
                int row = wm * 48 + mt * 16 + arow;
                uint32_t ab = (uint32_t)(row * 128 + ((kc8 ^ (row & 7)) << 4));
                LDSM_X4(af[mt][0], af[mt][1], af[mt][2], af[mt][3], sbase + G1_A + ab);
            }
            uint32_t bh[4], bl[4];
            {
                uint32_t ab = (uint32_t)((ks * 16 + bk) * 144 + (wn * 16 + bn8) * 2);
                LDSM_X4_T(bh[0], bh[1], bh[2], bh[3], sbase + G1_XH + ab);
                LDSM_X4_T(bl[0], bl[1], bl[2], bl[3], sbase + G1_XL + ab);
            }
#pragma unroll
            for (int mt = 0; mt < 3; mt++)
#pragma unroll
                for (int nt = 0; nt < 2; nt++) {
                    MMA_BF16(acc[mt][nt], af[mt], bh[2 * nt], bh[2 * nt + 1]);
                    MMA_BF16(acc[mt][nt], af[mt], bl[2 * nt], bl[2 * nt + 1]);
                }
        }
    }

    const int g = blockIdx.y;
    int crow = wm * 48 + (lane >> 2);
    int ccol = (lane & 3) * 2;
#pragma unroll
    for (int mt = 0; mt < 3; mt++) {
        int c0 = crow + mt * 16;
#pragma unroll
        for (int nt = 0; nt < 2; nt++) {
            int d = d0 + wn * 16 + nt * 8 + ccol;
            if (c0 < NC) {
                g_part[g][c0][d]     = acc[mt][nt][0];
                g_part[g][c0][d + 1] = acc[mt][nt][1];
            }
            if (c0 + 8 < NC) {
                g_part[g][c0 + 8][d]     = acc[mt][nt][2];
                g_part[g][c0 + 8][d + 1] = acc[mt][nt][3];
            }
        }
    }
}

// ---------------- reduce partials -> normalized bf16 hi/lo anchors (+ parallel npairs) ----------------
__global__ void k_anchor() {
    int c = blockIdx.x;
    int tid = threadIdx.x;
    int lane = tid & 31;
    __shared__ float sred[32];
    __shared__ int snp[32];
    __shared__ float s_scale;
    __shared__ int s_count;

    if (c >= NC) {
        if (tid < D_DIM) {
            g_aHi[c][tid] = __float2bfloat16(0.f);
            g_aLo[c][tid] = __float2bfloat16(0.f);
        }
        if (tid == 0) g_actInf[c] = NEGINF;
        if (c == CP - 1) {
            // parallel npairs reduction over g_cntp[64][65]
            const int* flat = &g_cntp[0][0];
            int np = 0;
            for (int i = tid; i < 64 * 65; i += 1024) np += flat[i];
#pragma unroll
            for (int o = 16; o; o >>= 1) np += __shfl_xor_sync(~0u, np, o);
            if (lane == 0) snp[tid >> 5] = np;
            __syncthreads();
            if (tid == 0) {
                long long t = 0;
                for (int i = 0; i < 32; i++) t += snp[i];
                g_npairs = t;
            }
        }
        return;
    }
    if (tid == 0) {
        int t = 0;
#pragma unroll
        for (int b = 0; b < 64; b++) t += g_cntp[b][c];
        s_count = t;
    }
    __syncthreads();
    int cnt = s_count;
    float inv = 1.0f / (float)max(cnt, 1);

    float s = 0.f;
#pragma unroll
    for (int g = 0; g < NG1; g++) s += g_part[g][c][tid];
    float a = s * inv;
    float ss = a * a;
#pragma unroll
    for (int o = 16; o; o >>= 1) ss += __shfl_xor_sync(~0u, ss, o);
    if ((tid & 31) == 0) sred[tid >> 5] = ss;
    __syncthreads();
    if (tid == 0) {
        float t = 0.f;
        for (int i = 0; i < 32; i++) t += sred[i];
        s_scale = 1.0f / fmaxf(sqrtf(t), EPSV);
        g_actInf[c] = (cnt > 0) ? 0.f : NEGINF;
    }
    __syncthreads();
    float av = a * s_scale;
    __nv_bfloat16 h = __float2bfloat16(av);
    g_aHi[c][tid] = h;
    g_aLo[c][tid] = __float2bfloat16(av - __bfloat162float(h));
}

// ---------------- GEMM2: double-buffered warp-MMA + fused epilogue + last-CTA finalize ----------------
#define S2_XH0 0
#define S2_XL0 8192
#define S2_XH1 16384
#define S2_XL1 24576
#define S2_B0  32768    // BH0; BL0 at +12288
#define S2_B1  57344    // BH1; BL1 at +12288
#define S2_LS  81920
#define S2_NRM 81984
#define S2_SZ  82240

__global__ __launch_bounds__(256, 2)
void k_gemm2_mma(const float* __restrict__ x,
                 const float* __restrict__ wp, const float* __restrict__ bp,
                 float* __restrict__ out) {
    extern __shared__ __align__(16) char sm[];
    const uint32_t sbase = smem_u32(sm);
    const int tid = threadIdx.x, wid = tid >> 5, lane = tid & 31;
    const int wr = wid & 3, wc = wid >> 2;
    const int rbase = blockIdx.x * 64;

    float acc[5][4];
#pragma unroll
    for (int j = 0; j < 5; j++)
#pragma unroll
        for (int e = 0; e < 4; e++) acc[j][e] = 0.f;

    float fsq[4];
#pragma unroll
    for (int j = 0; j < 4; j++) fsq[j] = 0.f;

    const int lsub = lane >> 3, lrr = lane & 7;
    const int arow_off = lrr + (lsub & 1) * 8;
    const int kgrp_sel = lsub >> 1;
    const int t16 = tid & 15, rq = tid >> 4;
    const int ki = 2 * t16;
    const int l16 = lane & 15;
    const int n2row = wc * 40 + 32 + (l16 & 7);
    const int kh2 = l16 >> 3;

    float4 pfx[4];
    uint2 pbh[5], pbl[5];

    // ---- prologue: load + store chunk 0 into buffer 0 ----
#pragma unroll
    for (int j = 0; j < 4; j++)
        pfx[j] = *(const float4*)(x + (size_t)(rbase + rq + 16 * j) * D_DIM + 4 * t16);
#pragma unroll
    for (int j = 0; j < 5; j++) {
        int c = (tid >> 4) + 16 * j;
        pbh[j] = *(const uint2*)&g_aHi[c][2 * ki];
        pbl[j] = *(const uint2*)&g_aLo[c][2 * ki];
    }
#pragma unroll
    for (int j = 0; j < 4; j++) {
        int r = rq + 16 * j;
        float4 v = pfx[j];
        fsq[j] += v.x * v.x + v.y * v.y + v.z * v.z + v.w * v.w;
        uint32_t off = (uint32_t)(r * 128 + (((ki >> 2) ^ (r & 7)) << 4) + ((ki & 3) << 2));
        __nv_bfloat16 h0 = __float2bfloat16(v.x), h1 = __float2bfloat16(v.y);
        __nv_bfloat16 h2 = __float2bfloat16(v.z), h3 = __float2bfloat16(v.w);
        __nv_bfloat162 w0; w0.x = h0; w0.y = h1;
        __nv_bfloat162 w1; w1.x = h2; w1.y = h3;
        *(__nv_bfloat162*)(sm + S2_XH0 + off)     = w0;
        *(__nv_bfloat162*)(sm + S2_XH0 + off + 4) = w1;
        w0.x = __float2bfloat16(v.x - __bfloat162float(h0));
        w0.y = __float2bfloat16(v.y - __bfloat162float(h1));
        w1.x = __float2bfloat16(v.z - __bfloat162float(h2));
        w1.y = __float2bfloat16(v.w - __bfloat162float(h3));
        *(__nv_bfloat162*)(sm + S2_XL0 + off)     = w0;
        *(__nv_bfloat162*)(sm + S2_XL0 + off + 4) = w1;
    }
#pragma unroll
    for (int j = 0; j < 5; j++) {
        int c = (tid >> 4) + 16 * j;
        uint32_t off = (uint32_t)(c * 128 + (((ki >> 2) ^ (c & 7)) << 4) + ((ki & 3) << 2));
        *(uint2*)(sm + S2_B0 + off) = pbh[j];
        *(uint2*)(sm + S2_B0 + 12288 + off) = pbl[j];
    }
    __syncthreads();

#pragma unroll 1
    for (int ch = 0; ch < 16; ch++) {
        const uint32_t bx = (ch & 1) ? 16384u : 0u;           // XH base; XL = +8192
        const uint32_t bb = (ch & 1) ? (uint32_t)S2_B1 : (uint32_t)S2_B0;

        if (ch < 15) {
            const int dn = (ch + 1) * 64;
            const float* xp = x + (size_t)(rbase + rq) * D_DIM + dn + 4 * t16;
#pragma unroll
            for (int j = 0; j < 4; j++)
                pfx[j] = *(const float4*)(xp + (size_t)(16 * j) * D_DIM);
#pragma unroll
            for (int j = 0; j < 5; j++) {
                int c = (tid >> 4) + 16 * j;
                pbh[j] = *(const uint2*)&g_aHi[c][dn + 2 * ki];
                pbl[j] = *(const uint2*)&g_aLo[c][dn + 2 * ki];
            }
        }

#pragma unroll
        for (int ks = 0; ks < 4; ks++) {
            const int kc8 = 2 * ks + kgrp_sel;
            uint32_t fh[4], fl[4];
            {
                int row = wr * 16 + arow_off;
                uint32_t ab = (uint32_t)(row * 128 + ((kc8 ^ (row & 7)) << 4));
                LDSM_X4(fh[0], fh[1], fh[2], fh[3], sbase + bx + ab);
                LDSM_X4(fl[0], fl[1], fl[2], fl[3], sbase + bx + 8192 + ab);
            }
            uint32_t bhf[2][4], blf[2][4];
#pragma unroll
            for (int p = 0; p < 2; p++) {
                int n = wc * 40 + p * 16 + arow_off;
                uint32_t ab = (uint32_t)(n * 128 + ((kc8 ^ (n & 7)) << 4));
                LDSM_X4(bhf[p][0], bhf[p][1], bhf[p][2], bhf[p][3], sbase + bb + ab);
                LDSM_X4(blf[p][0], blf[p][1], blf[p][2], blf[p][3], sbase + bb + 12288 + ab);
            }
            uint32_t bh2[2], bl2[2];
            {
                const int kc8b = 2 * ks + kh2;
                uint32_t ab2 = (uint32_t)(n2row * 128 + ((kc8b ^ (n2row & 7)) << 4));
                LDSM_X2(bh2[0], bh2[1], sbase + bb + ab2);
                LDSM_X2(bl2[0], bl2[1], sbase + bb + 12288 + ab2);
            }
#pragma unroll
            for (int nt = 0; nt < 4; nt++) {
                int p = nt >> 1, w2 = nt & 1;
                MMA_BF16(acc[nt], fh, bhf[p][w2], bhf[p][2 + w2]);
                MMA_BF16(acc[nt], fh, blf[p][w2], blf[p][2 + w2]);
                MMA_BF16(acc[nt], fl, bhf[p][w2], bhf[p][2 + w2]);
            }
            MMA_BF16(acc[4], fh, bh2[0], bh2[1]);
            MMA_BF16(acc[4], fh, bl2[0], bl2[1]);
            MMA_BF16(acc[4], fl, bh2[0], bh2[1]);
        }

        if (ch < 15) {
            const uint32_t nx = (ch & 1) ? 0u : 16384u;
            const uint32_t nb = (ch & 1) ? (uint32_t)S2_B0 : (uint32_t)S2_B1;
#pragma unroll
            for (int j = 0; j < 4; j++) {
                int r = rq + 16 * j;
                float4 v = pfx[j];
                fsq[j] += v.x * v.x + v.y * v.y + v.z * v.z + v.w * v.w;
                uint32_t off = (uint32_t)(r * 128 + (((ki >> 2) ^ (r & 7)) << 4) + ((ki & 3) << 2));
                __nv_bfloat16 h0 = __float2bfloat16(v.x), h1 = __float2bfloat16(v.y);
                __nv_bfloat16 h2 = __float2bfloat16(v.z), h3 = __float2bfloat16(v.w);
                __nv_bfloat162 w0; w0.x = h0; w0.y = h1;
                __nv_bfloat162 w1; w1.x = h2; w1.y = h3;
                *(__nv_bfloat162*)(sm + nx + off)            = w0;
                *(__nv_bfloat162*)(sm + nx + off + 4)        = w1;
                w0.x = __float2bfloat16(v.x - __bfloat162float(h0));
                w0.y = __float2bfloat16(v.y - __bfloat162float(h1));
                w1.x = __float2bfloat16(v.z - __bfloat162float(h2));
                w1.y = __float2bfloat16(v.w - __bfloat162float(h3));
                *(__nv_bfloat162*)(sm + nx + 8192 + off)     = w0;
                *(__nv_bfloat162*)(sm + nx + 8192 + off + 4) = w1;
            }
#pragma unroll
            for (int j = 0; j < 5; j++) {
                int c = (tid >> 4) + 16 * j;
                uint32_t off = (uint32_t)(c * 128 + (((ki >> 2) ^ (c & 7)) << 4) + ((ki & 3) << 2));
                *(uint2*)(sm + nb + off) = pbh[j];
                *(uint2*)(sm + nb + 12288 + off) = pbl[j];
            }
        }
        __syncthreads();
    }

    // row norms
#pragma unroll
    for (int j = 0; j < 4; j++) {
        float s = fsq[j];
        s += __shfl_xor_sync(~0u, s, 8);
        s += __shfl_xor_sync(~0u, s, 4);
        s += __shfl_xor_sync(~0u, s, 2);
        s += __shfl_xor_sync(~0u, s, 1);
        if (t16 == 0)
            *(float*)(sm + S2_NRM + (rq + 16 * j) * 4) = 1.0f / fmaxf(sqrtf(s), EPSV);
    }

    __syncthreads();
    float* sd = (float*)sm;      // [64][81] = 20736 B, overlays X buffers
    {
        int g = lane >> 2, t = lane & 3;
#pragma unroll
        for (int nt = 0; nt < 5; nt++) {
            int r0 = wr * 16 + g;
            int col = wc * 40 + nt * 8 + 2 * t;
            sd[r0 * 81 + col]           = acc[nt][0];
            sd[r0 * 81 + col + 1]       = acc[nt][1];
            sd[(r0 + 8) * 81 + col]     = acc[nt][2];
            sd[(r0 + 8) * 81 + col + 1] = acc[nt][3];
        }
    }
    __syncthreads();

    float wv = *wp, bv = *bp;
    double wl = 0.0;
    float aI0 = g_actInf[lane];
    float aI1 = g_actInf[lane + 32];
    float aI2 = (lane < 16) ? g_actInf[lane + 64] : NEGINF;

    for (int i = 0; i < 8; i++) {
        int rl = wid * 8 + i;
        int rg = rbase + rl;
        float xni = *(const float*)(sm + S2_NRM + rl * 4);
        ull m = g_mask[rg];
        float sw = xni * wv;

        float v0 = sd[rl * 81 + lane] * sw + bv + aI0;
        float v1 = sd[rl * 81 + lane + 32] * sw + bv + aI1;
        float v2 = (lane < 16) ? (sd[rl * 81 + lane + 64] * sw + bv + aI2) : NEGINF;

        float mx = fmaxf(v0, fmaxf(v1, v2));
#pragma unroll
        for (int o = 16; o; o >>= 1) mx = fmaxf(mx, __shfl_xor_sync(~0u, mx, o));

        float se = expf(v0 - mx) + expf(v1 - mx) + ((lane < 16) ? expf(v2 - mx) : 0.f);
#pragma unroll
        for (int o = 16; o; o >>= 1) se += __shfl_xor_sync(~0u, se, o);
        float lse = mx + logf(se);

        int b0 = (int)((m >> lane) & 1ull);
        int b1 = (int)((m >> (lane + 32)) & 1ull);
        int b2 = (lane == 0) ? (int)(m == 0ull) : 0;
        float sv = (b0 ? v0 : 0.f) + (b1 ? v1 : 0.f) + (b2 ? v2 : 0.f);
        int np = b0 + b1 + b2;
#pragma unroll
        for (int o = 16; o; o >>= 1) {
            sv += __shfl_xor_sync(~0u, sv, o);
            np += __shfl_xor_sync(~0u, np, o);
        }
        if (lane == 0) wl += (double)((float)np * lse - sv);
    }
    if (lane == 0) *(double*)(sm + S2_LS + wid * 8) = wl;
    __syncthreads();
    if (tid == 0) {
        double t = 0.0;
        for (int i = 0; i < 8; i++) t += *(double*)(sm + S2_LS + i * 8);
        atomicAdd(&g_lossSum, t);
        __threadfence();
        unsigned prev = atomicAdd(&g_done, 1u);
        if (prev == gridDim.x - 1) {
            double ls = atomicAdd(&g_lossSum, 0.0);   // coherent read
            out[0] = (float)(ls / (double)g_npairs);
        }
    }
}

// ---------------- launcher ----------------
extern "C" void kernel_launch(void* const* d_in, const int* in_sizes, int n_in,
                              void* d_out, int out_size) {
    const float* x = nullptr;
    const int* label = nullptr;
    const float* wp = nullptr;
    const float* bp = nullptr;
    for (int i = 0; i < n_in; i++) {
        if (in_sizes[i] == B_ROWS * D_DIM) x = (const float*)d_in[i];
        else if (in_sizes[i] == B_ROWS * 64) label = (const int*)d_in[i];
        else if (in_sizes[i] == 1) {
            if (!wp) wp = (const float*)d_in[i];
            else bp = (const float*)d_in[i];
        }
    }
    static int smem_set = 0;
    if (!smem_set) {
        cudaFuncSetAttribute(k_gemm2_mma, cudaFuncAttributeMaxDynamicSharedMemorySize, S2_SZ);
        cudaFuncSetAttribute(k_gemm1_mma, cudaFuncAttributeMaxDynamicSharedMemorySize, G1_SZ);
        smem_set = 1;
    }

    k_meta<<<64, 256>>>(label);
    k_gemm1_mma<<<dim3(16, NG1), 256, G1_SZ>>>(x);
    k_anchor<<<CP, 1024>>>();
    k_gemm2_mma<<<B_ROWS / 64, 256, S2_SZ>>>(x, wp, bp, (float*)d_out);
}

// round 17
// speedup vs baseline: 1.5331x; 1.0133x over previous
#include <cuda_runtime.h>
#include <cuda_bf16.h>
#include <cstdint>

typedef unsigned long long ull;

#define B_ROWS 16384
#define D_DIM  1024
#define NC     65      // 64 labels + "no-label" extra column
#define CP     80      // padded classes
#define NG1    16      // GEMM1 row groups (1024 rows each)
#define EPSV   1e-8f
#define NEGINF __int_as_float(0xff800000)

// warp-level tensor core helpers (base PTX, lowers to HMMA on sm_103)
#define LDSM_X4(r0, r1, r2, r3, a) \
    asm volatile("ldmatrix.sync.aligned.m8n8.x4.shared.b16 {%0,%1,%2,%3}, [%4];" \
        : "=r"(r0), "=r"(r1), "=r"(r2), "=r"(r3) : "r"(a))
#define LDSM_X2(r0, r1, a) \
    asm volatile("ldmatrix.sync.aligned.m8n8.x2.shared.b16 {%0,%1}, [%2];" \
        : "=r"(r0), "=r"(r1) : "r"(a))
#define LDSM_X4_T(r0, r1, r2, r3, a) \
    asm volatile("ldmatrix.sync.aligned.m8n8.x4.trans.shared.b16 {%0,%1,%2,%3}, [%4];" \
        : "=r"(r0), "=r"(r1), "=r"(r2), "=r"(r3) : "r"(a))
#define MMA_BF16(c, a, b0, b1) \
    asm volatile("mma.sync.aligned.m16n8k16.row.col.f32.bf16.bf16.f32 " \
        "{%0,%1,%2,%3}, {%4,%5,%6,%7}, {%8,%9}, {%0,%1,%2,%3};" \
        : "+f"((c)[0]), "+f"((c)[1]), "+f"((c)[2]), "+f"((c)[3]) \
        : "r"((a)[0]), "r"((a)[1]), "r"((a)[2]), "r"((a)[3]), "r"(b0), "r"(b1))

__device__ __forceinline__ uint32_t smem_u32(const void* p) {
    uint32_t a;
    asm("{ .reg .u64 t; cvta.to.shared.u64 t, %1; cvt.u32.u64 %0, t; }" : "=r"(a) : "l"(p));
    return a;
}

// pack x4 fp32 -> (hi bf16x2 pair, lo bf16x2 pair) as two uint2 for 8B stores
__device__ __forceinline__ void split4(float4 v, uint2& uh, uint2& ul) {
    __nv_bfloat162 h01 = __floats2bfloat162_rn(v.x, v.y);
    __nv_bfloat162 h23 = __floats2bfloat162_rn(v.z, v.w);
    float lx = v.x - __bfloat162float(__low2bfloat16(h01));
    float ly = v.y - __bfloat162float(__high2bfloat16(h01));
    float lz = v.z - __bfloat162float(__low2bfloat16(h23));
    float lw = v.w - __bfloat162float(__high2bfloat16(h23));
    __nv_bfloat162 l01 = __floats2bfloat162_rn(lx, ly);
    __nv_bfloat162 l23 = __floats2bfloat162_rn(lz, lw);
    uh.x = *(uint32_t*)&h01; uh.y = *(uint32_t*)&h23;
    ul.x = *(uint32_t*)&l01; ul.y = *(uint32_t*)&l23;
}

// ---------------- static device scratch ----------------
__device__ ull    g_mask[B_ROWS];
__device__ int    g_cntp[64][65];
__device__ float  g_part[NG1][CP][D_DIM];   // GEMM1 partial sums (5.2 MB)
__device__ __nv_bfloat16 g_aHi[CP][D_DIM];
__device__ __nv_bfloat16 g_aLo[CP][D_DIM];
__device__ float  g_actInf[CP];
__device__ double g_lossSum;
__device__ long long g_npairs;
__device__ unsigned g_done;

// ---------------- meta: labels -> masks, per-block class counts, zero accumulators ----------------
__global__ void k_meta(const int* __restrict__ label) {
    __shared__ int s_cnt[65];
    int tid = threadIdx.x, b = blockIdx.x, lane = tid & 31;
    int row = b * 256 + tid;

    const uint4* lr = (const uint4*)(label + (size_t)row * 64);
    ull m = 0ull;
#pragma unroll
    for (int i = 0; i < 16; i++) {
        uint4 v = lr[i];
        m |= ((ull)(v.x != 0) << (4 * i))     | ((ull)(v.y != 0) << (4 * i + 1))
           | ((ull)(v.z != 0) << (4 * i + 2)) | ((ull)(v.w != 0) << (4 * i + 3));
    }
    g_mask[row] = m;

    if (tid < 65) s_cnt[tid] = 0;
    __syncthreads();

    int ca = 0, cb = 0, cz = 0;
#pragma unroll
    for (int c = 0; c < 32; c++) {
        unsigned bal = __ballot_sync(~0u, (int)((m >> c) & 1ull));
        if (lane == c) ca = __popc(bal);
    }
#pragma unroll
    for (int c = 32; c < 64; c++) {
        unsigned bal = __ballot_sync(~0u, (int)((m >> c) & 1ull));
        if (lane == c - 32) cb = __popc(bal);
    }
    {
        unsigned bal = __ballot_sync(~0u, m == 0ull);
        if (lane == 0) cz = __popc(bal);
    }
    atomicAdd(&s_cnt[lane], ca);
    atomicAdd(&s_cnt[lane + 32], cb);
    if (lane == 0) atomicAdd(&s_cnt[64], cz);
    __syncthreads();
    if (tid < 65) g_cntp[b][tid] = s_cnt[tid];
    if (b == 0 && tid == 0) { g_lossSum = 0.0; g_done = 0u; }
}

// ---------------- GEMM1 via warp-MMA, 64-d tiles, 2 CTAs/SM ----------------
#define G1_XH 0        // [64 r][144 B]
#define G1_XL 9216
#define G1_A  18432    // [96 c][128 B] swizzled
#define G1_SZ 30720

__global__ __launch_bounds__(256, 2)
void k_gemm1_mma(const float* __restrict__ x) {
    extern __shared__ __align__(16) char sm[];
    const uint32_t sbase = smem_u32(sm);
    const int tid = threadIdx.x, wid = tid >> 5, lane = tid & 31;
    const int wm = wid & 1, wn = wid >> 1;
    const int d0 = blockIdx.x * 64;
    const int R0 = blockIdx.y * 1024;

    float acc[3][2][4];
#pragma unroll
    for (int i = 0; i < 3; i++)
#pragma unroll
        for (int j = 0; j < 2; j++)
#pragma unroll
            for (int e = 0; e < 4; e++) acc[i][j][e] = 0.f;

    const int lsub = lane >> 3, lrr = lane & 7;
    const int arow = lrr + (lsub & 1) * 8;
    const int kgrp = lsub >> 1;
    const int bk  = (lsub & 1) * 8 + lrr;
    const int bn8 = (lsub >> 1) * 8;
    const int k2 = tid & 31;
    const int t16 = tid & 15, rq = tid >> 4;

    float4 pf[4];
#pragma unroll
    for (int j = 0; j < 4; j++)
        pf[j] = *(const float4*)(x + (size_t)(R0 + rq + 16 * j) * D_DIM + d0 + 4 * t16);

#pragma unroll 1
    for (int ch = 0; ch < 16; ch++) {
        const int R = R0 + ch * 64;
        __syncthreads();
#pragma unroll
        for (int j = 0; j < 4; j++) {
            int r = rq + 16 * j;
            uint2 uh, ul;
            split4(pf[j], uh, ul);
            uint32_t off = (uint32_t)(r * 144 + t16 * 8);
            *(uint2*)(sm + G1_XH + off) = uh;
            *(uint2*)(sm + G1_XL + off) = ul;
        }
        {
            ull m0 = g_mask[R + 2 * k2], m1 = g_mask[R + 2 * k2 + 1];
#pragma unroll
            for (int j = 0; j < 12; j++) {
                int c = (tid >> 5) + 8 * j;
                uint32_t w = 0;
                if (c < 64)
                    w = (((m0 >> c) & 1ull) ? 0x3F80u : 0u) | (((m1 >> c) & 1ull) ? 0x3F800000u : 0u);
                else if (c == 64)
                    w = ((m0 == 0ull) ? 0x3F80u : 0u) | ((m1 == 0ull) ? 0x3F800000u : 0u);
                uint32_t off = (uint32_t)(c * 128 + (((k2 >> 2) ^ (c & 7)) << 4) + ((k2 & 3) << 2));
                *(uint32_t*)(sm + G1_A + off) = w;
            }
        }
        __syncthreads();

        if (ch < 15) {
            const float* xp = x + (size_t)(R + 64 + rq) * D_DIM + d0 + 4 * t16;
#pragma unroll
            for (int j = 0; j < 4; j++)
                pf[j] = *(const float4*)(xp + (size_t)(16 * j) * D_DIM);
        }

#pragma unroll
        for (int ks = 0; ks < 4; ks++) {
            const int kc8 = 2 * ks + kgrp;
            uint32_t af[3][4];
#pragma unroll
            for (int mt = 0; mt < 3; mt++) {
                int row = wm * 48 + mt * 16 + arow;
                uint32_t ab = (uint32_t)(row * 128 + ((kc8 ^ (row & 7)) << 4));
                LDSM_X4(af[mt][0], af[mt][1], af[mt][2], af[mt][3], sbase + G1_A + ab);
            }
            uint32_t bh[4], bl[4];
            {
                uint32_t ab = (uint32_t)((ks * 16 + bk) * 144 + (wn * 16 + bn8) * 2);
                LDSM_X4_T(bh[0], bh[1], bh[2], bh[3], sbase + G1_XH + ab);
                LDSM_X4_T(bl[0], bl[1], bl[2], bl[3], sbase + G1_XL + ab);
            }
#pragma unroll
            for (int mt = 0; mt < 3; mt++)
#pragma unroll
                for (int nt = 0; nt < 2; nt++) {
                    MMA_BF16(acc[mt][nt], af[mt], bh[2 * nt], bh[2 * nt + 1]);
                    MMA_BF16(acc[mt][nt], af[mt], bl[2 * nt], bl[2 * nt + 1]);
                }
        }
    }

    const int g = blockIdx.y;
    int crow = wm * 48 + (lane >> 2);
    int ccol = (lane & 3) * 2;
#pragma unroll
    for (int mt = 0; mt < 3; mt++) {
        int c0 = crow + mt * 16;
#pragma unroll
        for (int nt = 0; nt < 2; nt++) {
            int d = d0 + wn * 16 + nt * 8 + ccol;
            if (c0 < NC) {
                g_part[g][c0][d]     = acc[mt][nt][0];
                g_part[g][c0][d + 1] = acc[mt][nt][1];
            }
            if (c0 + 8 < NC) {
                g_part[g][c0 + 8][d]     = acc[mt][nt][2];
                g_part[g][c0 + 8][d + 1] = acc[mt][nt][3];
            }
        }
    }
}

// ---------------- reduce partials -> normalized bf16 hi/lo anchors (+ parallel npairs) ----------------
__global__ void k_anchor() {
    int c = blockIdx.x;
    int tid = threadIdx.x;
    int lane = tid & 31;
    __shared__ float sred[32];
    __shared__ int snp[32];
    __shared__ float s_scale;
    __shared__ int s_count;

    if (c >= NC) {
        if (tid < D_DIM) {
            g_aHi[c][tid] = __float2bfloat16(0.f);
            g_aLo[c][tid] = __float2bfloat16(0.f);
        }
        if (tid == 0) g_actInf[c] = NEGINF;
        if (c == CP - 1) {
            const int* flat = &g_cntp[0][0];
            int np = 0;
            for (int i = tid; i < 64 * 65; i += 1024) np += flat[i];
#pragma unroll
            for (int o = 16; o; o >>= 1) np += __shfl_xor_sync(~0u, np, o);
            if (lane == 0) snp[tid >> 5] = np;
            __syncthreads();
            if (tid == 0) {
                long long t = 0;
                for (int i = 0; i < 32; i++) t += snp[i];
                g_npairs = t;
            }
        }
        return;
    }
    if (tid == 0) {
        int t = 0;
#pragma unroll
        for (int b = 0; b < 64; b++) t += g_cntp[b][c];
        s_count = t;
    }
    __syncthreads();
    int cnt = s_count;
    float inv = 1.0f / (float)max(cnt, 1);

    float s = 0.f;
#pragma unroll
    for (int g = 0; g < NG1; g++) s += g_part[g][c][tid];
    float a = s * inv;
    float ss = a * a;
#pragma unroll
    for (int o = 16; o; o >>= 1) ss += __shfl_xor_sync(~0u, ss, o);
    if ((tid & 31) == 0) sred[tid >> 5] = ss;
    __syncthreads();
    if (tid == 0) {
        float t = 0.f;
        for (int i = 0; i < 32; i++) t += sred[i];
        s_scale = 1.0f / fmaxf(sqrtf(t), EPSV);
        g_actInf[c] = (cnt > 0) ? 0.f : NEGINF;
    }
    __syncthreads();
    float av = a * s_scale;
    __nv_bfloat16 h = __float2bfloat16(av);
    g_aHi[c][tid] = h;
    g_aLo[c][tid] = __float2bfloat16(av - __bfloat162float(h));
}

// ---------------- GEMM2: double-buffered warp-MMA + fused epilogue + last-CTA finalize ----------------
#define S2_XH0 0
#define S2_XL0 8192
#define S2_XH1 16384
#define S2_XL1 24576
#define S2_B0  32768    // BH0; BL0 at +12288
#define S2_B1  57344    // BH1; BL1 at +12288
#define S2_LS  81920
#define S2_NRM 81984
#define S2_SZ  82240

__global__ __launch_bounds__(256, 2)
void k_gemm2_mma(const float* __restrict__ x,
                 const float* __restrict__ wp, const float* __restrict__ bp,
                 float* __restrict__ out) {
    extern __shared__ __align__(16) char sm[];
    const uint32_t sbase = smem_u32(sm);
    const int tid = threadIdx.x, wid = tid >> 5, lane = tid & 31;
    const int wr = wid & 3, wc = wid >> 2;
    const int rbase = blockIdx.x * 64;

    float acc[5][4];
#pragma unroll
    for (int j = 0; j < 5; j++)
#pragma unroll
        for (int e = 0; e < 4; e++) acc[j][e] = 0.f;

    float fsq[4];
#pragma unroll
    for (int j = 0; j < 4; j++) fsq[j] = 0.f;

    const int lsub = lane >> 3, lrr = lane & 7;
    const int arow_off = lrr + (lsub & 1) * 8;
    const int kgrp_sel = lsub >> 1;
    const int t16 = tid & 15, rq = tid >> 4;
    const int ki = 2 * t16;
    const int l16 = lane & 15;
    const int n2row = wc * 40 + 32 + (l16 & 7);
    const int kh2 = l16 >> 3;

    float4 pfx[4];
    uint2 pbh[5], pbl[5];

    // ---- prologue: load + store chunk 0 into buffer 0 ----
#pragma unroll
    for (int j = 0; j < 4; j++)
        pfx[j] = *(const float4*)(x + (size_t)(rbase + rq + 16 * j) * D_DIM + 4 * t16);
#pragma unroll
    for (int j = 0; j < 5; j++) {
        int c = (tid >> 4) + 16 * j;
        pbh[j] = *(const uint2*)&g_aHi[c][2 * ki];
        pbl[j] = *(const uint2*)&g_aLo[c][2 * ki];
    }
#pragma unroll
    for (int j = 0; j < 4; j++) {
        int r = rq + 16 * j;
        float4 v = pfx[j];
        fsq[j] += v.x * v.x + v.y * v.y + v.z * v.z + v.w * v.w;
        uint2 uh, ul;
        split4(v, uh, ul);
        uint32_t off = (uint32_t)(r * 128 + (((ki >> 2) ^ (r & 7)) << 4) + ((ki & 3) << 2));
        *(uint2*)(sm + S2_XH0 + off) = uh;
        *(uint2*)(sm + S2_XL0 + off) = ul;
    }
#pragma unroll
    for (int j = 0; j < 5; j++) {
        int c = (tid >> 4) + 16 * j;
        uint32_t off = (uint32_t)(c * 128 + (((ki >> 2) ^ (c & 7)) << 4) + ((ki & 3) << 2));
        *(uint2*)(sm + S2_B0 + off) = pbh[j];
        *(uint2*)(sm + S2_B0 + 12288 + off) = pbl[j];
    }
    __syncthreads();

#pragma unroll 1
    for (int ch = 0; ch < 16; ch++) {
        const uint32_t bx = (ch & 1) ? 16384u : 0u;           // XH base; XL = +8192
        const uint32_t bb = (ch & 1) ? (uint32_t)S2_B1 : (uint32_t)S2_B0;

        if (ch < 15) {
            const int dn = (ch + 1) * 64;
            const float* xp = x + (size_t)(rbase + rq) * D_DIM + dn + 4 * t16;
#pragma unroll
            for (int j = 0; j < 4; j++)
                pfx[j] = *(const float4*)(xp + (size_t)(16 * j) * D_DIM);
#pragma unroll
            for (int j = 0; j < 5; j++) {
                int c = (tid >> 4) + 16 * j;
                pbh[j] = *(const uint2*)&g_aHi[c][dn + 2 * ki];
                pbl[j] = *(const uint2*)&g_aLo[c][dn + 2 * ki];
            }
        }

#pragma unroll
        for (int ks = 0; ks < 4; ks++) {
            const int kc8 = 2 * ks + kgrp_sel;
            uint32_t fh[4], fl[4];
            {
                int row = wr * 16 + arow_off;
                uint32_t ab = (uint32_t)(row * 128 + ((kc8 ^ (row & 7)) << 4));
                LDSM_X4(fh[0], fh[1], fh[2], fh[3], sbase + bx + ab);
                LDSM_X4(fl[0], fl[1], fl[2], fl[3], sbase + bx + 8192 + ab);
            }
            uint32_t bhf[2][4], blf[2][4];
#pragma unroll
            for (int p = 0; p < 2; p++) {
                int n = wc * 40 + p * 16 + arow_off;
                uint32_t ab = (uint32_t)(n * 128 + ((kc8 ^ (n & 7)) << 4));
                LDSM_X4(bhf[p][0], bhf[p][1], bhf[p][2], bhf[p][3], sbase + bb + ab);
                LDSM_X4(blf[p][0], blf[p][1], blf[p][2], blf[p][3], sbase + bb + 12288 + ab);
            }
            uint32_t bh2[2], bl2[2];
            {
                const int kc8b = 2 * ks + kh2;
                uint32_t ab2 = (uint32_t)(n2row * 128 + ((kc8b ^ (n2row & 7)) << 4));
                LDSM_X2(bh2[0], bh2[1], sbase + bb + ab2);
                LDSM_X2(bl2[0], bl2[1], sbase + bb + 12288 + ab2);
            }
#pragma unroll
            for (int nt = 0; nt < 4; nt++) {
                int p = nt >> 1, w2 = nt & 1;
                MMA_BF16(acc[nt], fh, bhf[p][w2], bhf[p][2 + w2]);
                MMA_BF16(acc[nt], fh, blf[p][w2], blf[p][2 + w2]);
                MMA_BF16(acc[nt], fl, bhf[p][w2], bhf[p][2 + w2]);
            }
            MMA_BF16(acc[4], fh, bh2[0], bh2[1]);
            MMA_BF16(acc[4], fh, bl2[0], bl2[1]);
            MMA_BF16(acc[4], fl, bh2[0], bh2[1]);
        }

        if (ch < 15) {
            const uint32_t nx = (ch & 1) ? 0u : 16384u;
            const uint32_t nb = (ch & 1) ? (uint32_t)S2_B0 : (uint32_t)S2_B1;
#pragma unroll
            for (int j = 0; j < 4; j++) {
                int r = rq + 16 * j;
                float4 v = pfx[j];
                fsq[j] += v.x * v.x + v.y * v.y + v.z * v.z + v.w * v.w;
                uint2 uh, ul;
                split4(v, uh, ul);
                uint32_t off = (uint32_t)(r * 128 + (((ki >> 2) ^ (r & 7)) << 4) + ((ki & 3) << 2));
                *(uint2*)(sm + nx + off) = uh;
                *(uint2*)(sm + nx + 8192 + off) = ul;
            }
#pragma unroll
            for (int j = 0; j < 5; j++) {
                int c = (tid >> 4) + 16 * j;
                uint32_t off = (uint32_t)(c * 128 + (((ki >> 2) ^ (c & 7)) << 4) + ((ki & 3) << 2));
                *(uint2*)(sm + nb + off) = pbh[j];
                *(uint2*)(sm + nb + 12288 + off) = pbl[j];
            }
        }
        __syncthreads();
    }

    // row norms
#pragma unroll
    for (int j = 0; j < 4; j++) {
        float s = fsq[j];
        s += __shfl_xor_sync(~0u, s, 8);
        s += __shfl_xor_sync(~0u, s, 4);
        s += __shfl_xor_sync(~0u, s, 2);
        s += __shfl_xor_sync(~0u, s, 1);
        if (t16 == 0)
            *(float*)(sm + S2_NRM + (rq + 16 * j) * 4) = 1.0f / fmaxf(sqrtf(s), EPSV);
    }

    __syncthreads();
    float* sd = (float*)sm;      // [64][81] = 20736 B, overlays X buffers
    {
        int g = lane >> 2, t = lane & 3;
#pragma unroll
        for (int nt = 0; nt < 5; nt++) {
            int r0 = wr * 16 + g;
            int col = wc * 40 + nt * 8 + 2 * t;
            sd[r0 * 81 + col]           = acc[nt][0];
            sd[r0 * 81 + col + 1]       = acc[nt][1];
            sd[(r0 + 8) * 81 + col]     = acc[nt][2];
            sd[(r0 + 8) * 81 + col + 1] = acc[nt][3];
        }
    }
    __syncthreads();

    float wv = *wp, bv = *bp;
    double wl = 0.0;
    float aI0 = g_actInf[lane];
    float aI1 = g_actInf[lane + 32];
    float aI2 = (lane < 16) ? g_actInf[lane + 64] : NEGINF;

    for (int i = 0; i < 8; i++) {
        int rl = wid * 8 + i;
        int rg = rbase + rl;
        float xni = *(const float*)(sm + S2_NRM + rl * 4);
        ull m = g_mask[rg];
        float sw = xni * wv;

        float v0 = sd[rl * 81 + lane] * sw + bv + aI0;
        float v1 = sd[rl * 81 + lane + 32] * sw + bv + aI1;
        float v2 = (lane < 16) ? (sd[rl * 81 + lane + 64] * sw + bv + aI2) : NEGINF;

        float mx = fmaxf(v0, fmaxf(v1, v2));
#pragma unroll
        for (int o = 16; o; o >>= 1) mx = fmaxf(mx, __shfl_xor_sync(~0u, mx, o));

        float se = expf(v0 - mx) + expf(v1 - mx) + ((lane < 16) ? expf(v2 - mx) : 0.f);
#pragma unroll
        for (int o = 16; o; o >>= 1) se += __shfl_xor_sync(~0u, se, o);
        float lse = mx + logf(se);

        int b0 = (int)((m >> lane) & 1ull);
        int b1 = (int)((m >> (lane + 32)) & 1ull);
        int b2 = (lane == 0) ? (int)(m == 0ull) : 0;
        float sv = (b0 ? v0 : 0.f) + (b1 ? v1 : 0.f) + (b2 ? v2 : 0.f);
        int np = b0 + b1 + b2;
#pragma unroll
        for (int o = 16; o; o >>= 1) {
            sv += __shfl_xor_sync(~0u, sv, o);
            np += __shfl_xor_sync(~0u, np, o);
        }
        if (lane == 0) wl += (double)((float)np * lse - sv);
    }
    if (lane == 0) *(double*)(sm + S2_LS + wid * 8) = wl;
    __syncthreads();
    if (tid == 0) {
        double t = 0.0;
        for (int i = 0; i < 8; i++) t += *(double*)(sm + S2_LS + i * 8);
        atomicAdd(&g_lossSum, t);
        __threadfence();
        unsigned prev = atomicAdd(&g_done, 1u);
        if (prev == gridDim.x - 1) {
            double ls = atomicAdd(&g_lossSum, 0.0);   // coherent read
            out[0] = (float)(ls / (double)g_npairs);
        }
    }
}

// ---------------- launcher ----------------
extern "C" void kernel_launch(void* const* d_in, const int* in_sizes, int n_in,
                              void* d_out, int out_size) {
    const float* x = nullptr;
    const int* label = nullptr;
    const float* wp = nullptr;
    const float* bp = nullptr;
    for (int i = 0; i < n_in; i++) {
        if (in_sizes[i] == B_ROWS * D_DIM) x = (const float*)d_in[i];
        else if (in_sizes[i] == B_ROWS * 64) label = (const int*)d_in[i];
        else if (in_sizes[i] == 1) {
            if (!wp) wp = (const float*)d_in[i];
            else bp = (const float*)d_in[i];
        }
    }
    static int smem_set = 0;
    if (!smem_set) {
        cudaFuncSetAttribute(k_gemm2_mma, cudaFuncAttributeMaxDynamicSharedMemorySize, S2_SZ);
        cudaFuncSetAttribute(k_gemm1_mma, cudaFuncAttributeMaxDynamicSharedMemorySize, G1_SZ);
        smem_set = 1;
    }

    k_meta<<<64, 256>>>(label);
    k_gemm1_mma<<<dim3(16, NG1), 256, G1_SZ>>>(x);
    k_anchor<<<CP, 1024>>>();
    k_gemm2_mma<<<B_ROWS / 64, 256, S2_SZ>>>(x, wp, bp, (float*)d_out);
}